// round 5
// baseline (speedup 1.0000x reference)
#include <cuda_runtime.h>
#include <cuda_bf16.h>
#include <math.h>

// Problem constants (shapes fixed by the dataset)
#define NMAX  100000
#define EMAX  1600000
#define F1    128
#define F2    64

// ---------------- scratch (static device globals; no allocation allowed) ----
__device__ int    g_is64;                 // 1 if edge_index is int64, else int32
__device__ int    g_cnt[NMAX];
__device__ int    g_rowstart[NMAX + 1];
__device__ int    g_cursor[NMAX];
__device__ float  g_dinv[NMAX];
__device__ int    g_rows[EMAX];
__device__ int    g_cols[EMAX];
__device__ int    g_csr[EMAX];
__device__ float4 g_h1s[(size_t)NMAX * F1 / 4];     // (x @ W1) * dinv[row]
__device__ float4 g_hidden[(size_t)NMAX * F1 / 4];  // relu(dinv*(sum)+b1)
__device__ float4 g_h2s[(size_t)NMAX * F2 / 4];     // (hidden @ W2) * dinv[row]

// ---------------- kernels ---------------------------------------------------

// Probe dtype of edge_index: as int64 (values < 2^31) every high 32-bit word
// is zero; as int32 random indices make that essentially impossible.
__global__ void k_detect(const int* __restrict__ ei_raw) {
    if (threadIdx.x == 0 && blockIdx.x == 0) {
        int any = 0;
        for (int i = 0; i < 64; i++) any |= ei_raw[2 * i + 1];
        g_is64 = (any == 0) ? 1 : 0;
    }
}

__global__ void k_zero_cnt(int N) {
    int i = blockIdx.x * blockDim.x + threadIdx.x;
    if (i < N) g_cnt[i] = 0;
}

// Decode edge indices (int32 or int64 per flag), validate, count in-degree.
__global__ void k_count(const void* __restrict__ ei_raw, int E, int N) {
    int e = blockIdx.x * blockDim.x + threadIdx.x;
    if (e >= E) return;
    int r, c;
    if (g_is64) {
        const long long* ei = (const long long*)ei_raw;
        r = (int)ei[e];
        c = (int)ei[(size_t)E + e];
    } else {
        const int* ei = (const int*)ei_raw;
        r = ei[e];
        c = ei[(size_t)E + e];
    }
    if ((unsigned)r >= (unsigned)N || (unsigned)c >= (unsigned)N) {
        g_rows[e] = -1; g_cols[e] = -1;   // defensive: never index with garbage
        return;
    }
    g_rows[e] = r;
    g_cols[e] = c;
    atomicAdd(&g_cnt[c], 1);
}

// Single-block exclusive scan over counts -> rowstart/cursor; also dinv.
__global__ void __launch_bounds__(1024) k_scan(int N) {
    __shared__ int part[1024];
    int tid = threadIdx.x;
    int chunk = (N + 1023) / 1024;
    int lo = tid * chunk;
    int hi = lo + chunk; if (hi > N) hi = N; if (lo > N) lo = N;
    int s = 0;
    for (int i = lo; i < hi; i++) s += g_cnt[i];
    part[tid] = s;
    __syncthreads();
    // Hillis-Steele inclusive scan
    for (int off = 1; off < 1024; off <<= 1) {
        int v = (tid >= off) ? part[tid - off] : 0;
        __syncthreads();
        part[tid] += v;
        __syncthreads();
    }
    int base = (tid == 0) ? 0 : part[tid - 1];
    for (int i = lo; i < hi; i++) {
        g_rowstart[i] = base;
        g_cursor[i]   = base;
        int c = g_cnt[i];
        g_dinv[i] = rsqrtf((float)(c + 1));   // +1 self loop; deg >= 1 always
        base += c;
    }
    if (tid == 1023) g_rowstart[N] = base;
}

// Fill CSR: for each valid edge, place its source row into target's bucket.
__global__ void k_fill(int E) {
    int e = blockIdx.x * blockDim.x + threadIdx.x;
    if (e < E) {
        int c = g_cols[e];
        if (c < 0) return;
        int pos = atomicAdd(&g_cursor[c], 1);
        g_csr[pos] = g_rows[e];
    }
}

// h1s[n, fhalf+f] = (x[n] @ W1[:, fhalf+f]) * dinv[n]
// blockIdx.y selects which 64-col half of W1 (32KB static smem tile).
// 4 nodes per block, 256 threads: tid = (node 0..3) * 64 + (feature 0..63).
__global__ void __launch_bounds__(256) k_gemm1(const float* __restrict__ x,
                                               const float* __restrict__ W1, int N) {
    __shared__ float W1s[F1 * 64];   // 32KB: W1[k][fhalf + 0..63]
    __shared__ float xrow[4][F1];    // 2KB
    int tid = threadIdx.x;
    int fhalf = blockIdx.y * 64;
    for (int j = tid; j < F1 * 64; j += 256) {
        int k = j >> 6, f = j & 63;
        W1s[j] = W1[k * F1 + fhalf + f];
    }
    int base = blockIdx.x * 4;
    for (int j = tid; j < 4 * F1; j += 256) {
        int r = j >> 7, c = j & 127;
        int nn = base + r;
        xrow[r][c] = (nn < N) ? x[(size_t)nn * F1 + c] : 0.f;
    }
    __syncthreads();
    int ns = tid >> 6;      // node sub-index 0..3
    int f  = tid & 63;      // output feature within half
    float acc = 0.f;
    #pragma unroll 8
    for (int k = 0; k < F1; k++)
        acc = fmaf(xrow[ns][k], W1s[k * 64 + f], acc);
    int n = base + ns;
    if (n < N) {
        float* h1s = (float*)g_h1s;
        h1s[(size_t)n * F1 + fhalf + f] = acc * g_dinv[n];
    }
}

// Aggregate layer 1: warp per node, register accumulation, fused relu+bias.
__global__ void __launch_bounds__(256) k_agg1(const float* __restrict__ b1, int N) {
    int lane  = threadIdx.x & 31;
    int warp  = (blockIdx.x * blockDim.x + threadIdx.x) >> 5;
    int nwarp = (gridDim.x * blockDim.x) >> 5;
    float bx = b1[4 * lane + 0], by = b1[4 * lane + 1];
    float bz = b1[4 * lane + 2], bw = b1[4 * lane + 3];
    for (int n = warp; n < N; n += nwarp) {
        float4 acc = g_h1s[(size_t)n * (F1 / 4) + lane];   // self loop
        int s = g_rowstart[n], e = g_rowstart[n + 1];
        for (int i = s; i < e; i++) {
            int src = g_csr[i];
            float4 v = g_h1s[(size_t)src * (F1 / 4) + lane];
            acc.x += v.x; acc.y += v.y; acc.z += v.z; acc.w += v.w;
        }
        float dn = g_dinv[n];
        float4 o;
        o.x = fmaxf(fmaf(dn, acc.x, bx), 0.f);
        o.y = fmaxf(fmaf(dn, acc.y, by), 0.f);
        o.z = fmaxf(fmaf(dn, acc.z, bz), 0.f);
        o.w = fmaxf(fmaf(dn, acc.w, bw), 0.f);
        g_hidden[(size_t)n * (F1 / 4) + lane] = o;
    }
}

// h2s[n] = (hidden[n] @ W2) * dinv[n].  W2 (32KB) in static smem; 4 nodes/block.
__global__ void __launch_bounds__(256) k_gemm2(const float* __restrict__ W2, int N) {
    __shared__ float W2s[F1 * F2];   // 32KB
    __shared__ float hid[4][F1];     // 2KB
    int tid = threadIdx.x;
    for (int i = tid; i < F1 * F2; i += 256) W2s[i] = W2[i];
    int base = blockIdx.x * 4;
    const float* hidden = (const float*)g_hidden;
    for (int j = tid; j < 4 * F1; j += 256) {
        int r = j >> 7, c = j & 127;
        int nn = base + r;
        hid[r][c] = (nn < N) ? hidden[(size_t)nn * F1 + c] : 0.f;
    }
    __syncthreads();
    int ns = tid >> 6;      // node sub-index 0..3
    int f  = tid & 63;      // output feature
    float acc = 0.f;
    #pragma unroll 8
    for (int k = 0; k < F1; k++)
        acc = fmaf(hid[ns][k], W2s[k * F2 + f], acc);
    int n = base + ns;
    if (n < N) {
        float* h2s = (float*)g_h2s;
        h2s[(size_t)n * F2 + f] = acc * g_dinv[n];
    }
}

// Aggregate layer 2: warp per node (float2 per lane), fused bias, write output.
__global__ void __launch_bounds__(256) k_agg2(const float* __restrict__ b2,
                                              float* __restrict__ out, int N) {
    int lane  = threadIdx.x & 31;
    int warp  = (blockIdx.x * blockDim.x + threadIdx.x) >> 5;
    int nwarp = (gridDim.x * blockDim.x) >> 5;
    float bx = b2[2 * lane + 0], by = b2[2 * lane + 1];
    const float2* h2s = (const float2*)g_h2s;
    for (int n = warp; n < N; n += nwarp) {
        float2 acc = h2s[(size_t)n * (F2 / 2) + lane];   // self loop
        int s = g_rowstart[n], e = g_rowstart[n + 1];
        for (int i = s; i < e; i++) {
            int src = g_csr[i];
            float2 v = h2s[(size_t)src * (F2 / 2) + lane];
            acc.x += v.x; acc.y += v.y;
        }
        float dn = g_dinv[n];
        out[(size_t)n * F2 + 2 * lane + 0] = fmaf(dn, acc.x, bx);
        out[(size_t)n * F2 + 2 * lane + 1] = fmaf(dn, acc.y, by);
    }
}

// ---------------- launcher ---------------------------------------------------

extern "C" void kernel_launch(void* const* d_in, const int* in_sizes, int n_in,
                              void* d_out, int out_size) {
    const float* x  = (const float*)d_in[0];
    const void*  ei = d_in[1];                 // int32 or int64 — probed on device
    // d_in[2] = edge_weight (unused: reference overwrites with ones)
    const float* W1 = (const float*)d_in[3];
    const float* b1 = (const float*)d_in[4];
    const float* W2 = (const float*)d_in[5];
    const float* b2 = (const float*)d_in[6];
    float*       out = (float*)d_out;

    int N = in_sizes[0] / F1;
    int E = in_sizes[1] / 2;
    if (N > NMAX) N = NMAX;
    if (E > EMAX) E = EMAX;

    k_detect<<<1, 32>>>((const int*)ei);
    k_zero_cnt<<<(N + 255) / 256, 256>>>(N);
    k_count<<<(E + 255) / 256, 256>>>(ei, E, N);
    k_scan<<<1, 1024>>>(N);
    k_fill<<<(E + 255) / 256, 256>>>(E);

    dim3 g1((N + 3) / 4, 2);
    k_gemm1<<<g1, 256>>>(x, W1, N);
    k_agg1<<<(N + 7) / 8, 256>>>(b1, N);
    k_gemm2<<<(N + 3) / 4, 256>>>(W2, N);
    k_agg2<<<(N + 7) / 8, 256>>>(b2, out, N);
}

// round 6
// speedup vs baseline: 1.5170x; 1.5170x over previous
#include <cuda_runtime.h>
#include <cuda_bf16.h>
#include <math.h>

// Problem constants (shapes fixed by the dataset)
#define NMAX  100000
#define EMAX  1600000
#define F1    128
#define F2    64
#define SCAN_B 512
#define NBMAX ((NMAX + SCAN_B - 1) / SCAN_B)   // 196

// ---------------- scratch (static device globals; no allocation allowed) ----
__device__ int    g_is64;                 // 1 if edge_index is int64, else int32
__device__ int    g_cnt[NMAX];
__device__ int    g_bsum[NBMAX];
__device__ int    g_boff[NBMAX];
__device__ int    g_rowstart[NMAX + 1];
__device__ int    g_cursor[NMAX];
__device__ float  g_dinv[NMAX];
__device__ int    g_rows[EMAX];
__device__ int    g_cols[EMAX];
__device__ int    g_csr[EMAX];
__device__ float4 g_h1s[(size_t)NMAX * F1 / 4];     // (x @ W1) * dinv[row]
__device__ float4 g_hidden[(size_t)NMAX * F1 / 4];  // relu(dinv*(sum)+b1)
__device__ float4 g_h2s[(size_t)NMAX * F2 / 4];     // (hidden @ W2) * dinv[row]

// ---------------- build kernels ---------------------------------------------

// Probe dtype of edge_index: int64 values < 2^31 have zero high words.
__global__ void k_detect(const int* __restrict__ ei_raw) {
    if (threadIdx.x == 0 && blockIdx.x == 0) {
        int any = 0;
        for (int i = 0; i < 64; i++) any |= ei_raw[2 * i + 1];
        g_is64 = (any == 0) ? 1 : 0;
    }
}

__global__ void k_zero_cnt(int N) {
    int i = blockIdx.x * blockDim.x + threadIdx.x;
    if (i < N) g_cnt[i] = 0;
}

// Decode edge indices (int32 or int64 per flag), validate, count in-degree.
__global__ void k_count(const void* __restrict__ ei_raw, int E, int N) {
    int e = blockIdx.x * blockDim.x + threadIdx.x;
    if (e >= E) return;
    int r, c;
    if (g_is64) {
        const long long* ei = (const long long*)ei_raw;
        r = (int)ei[e];
        c = (int)ei[(size_t)E + e];
    } else {
        const int* ei = (const int*)ei_raw;
        r = ei[e];
        c = ei[(size_t)E + e];
    }
    if ((unsigned)r >= (unsigned)N || (unsigned)c >= (unsigned)N) {
        g_rows[e] = -1; g_cols[e] = -1;
        return;
    }
    g_rows[e] = r;
    g_cols[e] = c;
    atomicAdd(&g_cnt[c], 1);
}

// Phase 1: per-block sums of counts.
__global__ void __launch_bounds__(SCAN_B) k_scan_partial(int N) {
    __shared__ int red[SCAN_B / 32];
    int b = blockIdx.x, tid = threadIdx.x;
    int i = b * SCAN_B + tid;
    int v = (i < N) ? g_cnt[i] : 0;
    for (int o = 16; o > 0; o >>= 1) v += __shfl_down_sync(0xffffffffu, v, o);
    if ((tid & 31) == 0) red[tid >> 5] = v;
    __syncthreads();
    if (tid < SCAN_B / 32) {
        int s = red[tid];
        for (int o = (SCAN_B / 64); o > 0; o >>= 1) s += __shfl_down_sync(0xffffu, s, o);
        if (tid == 0) g_bsum[b] = s;
    }
}

// Phase 2: single block scans block sums -> exclusive offsets; writes total.
__global__ void __launch_bounds__(256) k_scan_blk(int nb, int N) {
    __shared__ int sh[256];
    int tid = threadIdx.x;
    int v = (tid < nb) ? g_bsum[tid] : 0;
    sh[tid] = v;
    __syncthreads();
    for (int o = 1; o < 256; o <<= 1) {
        int t = (tid >= o) ? sh[tid - o] : 0;
        __syncthreads();
        sh[tid] += t;
        __syncthreads();
    }
    if (tid < nb) g_boff[tid] = sh[tid] - v;       // exclusive
    if (tid == 255) g_rowstart[N] = sh[255];       // total
}

// Phase 3: block-local exclusive scan + offset -> rowstart/cursor/dinv.
__global__ void __launch_bounds__(SCAN_B) k_scan_apply(int N) {
    __shared__ int sh[SCAN_B];
    int b = blockIdx.x, tid = threadIdx.x;
    int i = b * SCAN_B + tid;
    int v = (i < N) ? g_cnt[i] : 0;
    sh[tid] = v;
    __syncthreads();
    for (int o = 1; o < SCAN_B; o <<= 1) {
        int t = (tid >= o) ? sh[tid - o] : 0;
        __syncthreads();
        sh[tid] += t;
        __syncthreads();
    }
    if (i < N) {
        int base = g_boff[b] + sh[tid] - v;        // exclusive prefix
        g_rowstart[i] = base;
        g_cursor[i]   = base;
        g_dinv[i] = rsqrtf((float)(v + 1));        // +1 self loop
    }
}

// Fill CSR: for each valid edge, place its source row into target's bucket.
__global__ void k_fill(int E) {
    int e = blockIdx.x * blockDim.x + threadIdx.x;
    if (e < E) {
        int c = g_cols[e];
        if (c < 0) return;
        int pos = atomicAdd(&g_cursor[c], 1);
        g_csr[pos] = g_rows[e];
    }
}

// ---------------- compute kernels -------------------------------------------

// h1s[n, fhalf+f] = (x[n] @ W1[:, fhalf+f]) * dinv[n]
// Persistent: W half tile (32KB) loaded ONCE per block, grid-stride over nodes.
__global__ void __launch_bounds__(256) k_gemm1(const float* __restrict__ x,
                                               const float* __restrict__ W1, int N) {
    __shared__ float W1s[F1 * 64];   // 32KB: W1[k][fhalf + 0..63]
    __shared__ float xrow[4][F1];    // 2KB
    int tid = threadIdx.x;
    int fhalf = blockIdx.y * 64;
    for (int j = tid; j < F1 * 64; j += 256) {
        int k = j >> 6, f = j & 63;
        W1s[j] = W1[k * F1 + fhalf + f];
    }
    int ns = tid >> 6;      // node sub-index 0..3
    int f  = tid & 63;      // output feature within half
    float* h1s = (float*)g_h1s;
    for (int base = blockIdx.x * 4; base < N; base += gridDim.x * 4) {
        for (int j = tid; j < 4 * F1; j += 256) {
            int r = j >> 7, c = j & 127;
            int nn = base + r;
            xrow[r][c] = (nn < N) ? x[(size_t)nn * F1 + c] : 0.f;
        }
        __syncthreads();
        float acc = 0.f;
        #pragma unroll 16
        for (int k = 0; k < F1; k++)
            acc = fmaf(xrow[ns][k], W1s[k * 64 + f], acc);
        int n = base + ns;
        if (n < N) h1s[(size_t)n * F1 + fhalf + f] = acc * g_dinv[n];
        __syncthreads();
    }
}

// Aggregate layer 1: warp per node, 4-way unrolled gather, fused relu+bias.
__global__ void __launch_bounds__(256) k_agg1(const float* __restrict__ b1, int N) {
    int lane  = threadIdx.x & 31;
    int warp  = (blockIdx.x * blockDim.x + threadIdx.x) >> 5;
    int nwarp = (gridDim.x * blockDim.x) >> 5;
    float bx = b1[4 * lane + 0], by = b1[4 * lane + 1];
    float bz = b1[4 * lane + 2], bw = b1[4 * lane + 3];
    for (int n = warp; n < N; n += nwarp) {
        float4 acc = g_h1s[(size_t)n * (F1 / 4) + lane];   // self loop
        int s = g_rowstart[n], e = g_rowstart[n + 1];
        int i = s;
        for (; i + 4 <= e; i += 4) {
            int s0 = g_csr[i], s1 = g_csr[i + 1], s2 = g_csr[i + 2], s3 = g_csr[i + 3];
            float4 v0 = g_h1s[(size_t)s0 * (F1 / 4) + lane];
            float4 v1 = g_h1s[(size_t)s1 * (F1 / 4) + lane];
            float4 v2 = g_h1s[(size_t)s2 * (F1 / 4) + lane];
            float4 v3 = g_h1s[(size_t)s3 * (F1 / 4) + lane];
            acc.x += v0.x + v1.x + v2.x + v3.x;
            acc.y += v0.y + v1.y + v2.y + v3.y;
            acc.z += v0.z + v1.z + v2.z + v3.z;
            acc.w += v0.w + v1.w + v2.w + v3.w;
        }
        for (; i < e; i++) {
            int src = g_csr[i];
            float4 v = g_h1s[(size_t)src * (F1 / 4) + lane];
            acc.x += v.x; acc.y += v.y; acc.z += v.z; acc.w += v.w;
        }
        float dn = g_dinv[n];
        float4 o;
        o.x = fmaxf(fmaf(dn, acc.x, bx), 0.f);
        o.y = fmaxf(fmaf(dn, acc.y, by), 0.f);
        o.z = fmaxf(fmaf(dn, acc.z, bz), 0.f);
        o.w = fmaxf(fmaf(dn, acc.w, bw), 0.f);
        g_hidden[(size_t)n * (F1 / 4) + lane] = o;
    }
}

// h2s[n] = (hidden[n] @ W2) * dinv[n]. Persistent: W2 (32KB) loaded once.
__global__ void __launch_bounds__(256) k_gemm2(const float* __restrict__ W2, int N) {
    __shared__ float W2s[F1 * F2];   // 32KB
    __shared__ float hid[4][F1];     // 2KB
    int tid = threadIdx.x;
    for (int i = tid; i < F1 * F2; i += 256) W2s[i] = W2[i];
    int ns = tid >> 6;      // node sub-index 0..3
    int f  = tid & 63;      // output feature
    const float* hidden = (const float*)g_hidden;
    float* h2s = (float*)g_h2s;
    for (int base = blockIdx.x * 4; base < N; base += gridDim.x * 4) {
        for (int j = tid; j < 4 * F1; j += 256) {
            int r = j >> 7, c = j & 127;
            int nn = base + r;
            hid[r][c] = (nn < N) ? hidden[(size_t)nn * F1 + c] : 0.f;
        }
        __syncthreads();
        float acc = 0.f;
        #pragma unroll 16
        for (int k = 0; k < F1; k++)
            acc = fmaf(hid[ns][k], W2s[k * F2 + f], acc);
        int n = base + ns;
        if (n < N) h2s[(size_t)n * F2 + f] = acc * g_dinv[n];
        __syncthreads();
    }
}

// Aggregate layer 2: warp per node, 4-way unrolled gather, fused bias.
__global__ void __launch_bounds__(256) k_agg2(const float* __restrict__ b2,
                                              float* __restrict__ out, int N) {
    int lane  = threadIdx.x & 31;
    int warp  = (blockIdx.x * blockDim.x + threadIdx.x) >> 5;
    int nwarp = (gridDim.x * blockDim.x) >> 5;
    float bx = b2[2 * lane + 0], by = b2[2 * lane + 1];
    const float2* h2s = (const float2*)g_h2s;
    for (int n = warp; n < N; n += nwarp) {
        float2 acc = h2s[(size_t)n * (F2 / 2) + lane];   // self loop
        int s = g_rowstart[n], e = g_rowstart[n + 1];
        int i = s;
        for (; i + 4 <= e; i += 4) {
            int s0 = g_csr[i], s1 = g_csr[i + 1], s2 = g_csr[i + 2], s3 = g_csr[i + 3];
            float2 v0 = h2s[(size_t)s0 * (F2 / 2) + lane];
            float2 v1 = h2s[(size_t)s1 * (F2 / 2) + lane];
            float2 v2 = h2s[(size_t)s2 * (F2 / 2) + lane];
            float2 v3 = h2s[(size_t)s3 * (F2 / 2) + lane];
            acc.x += v0.x + v1.x + v2.x + v3.x;
            acc.y += v0.y + v1.y + v2.y + v3.y;
        }
        for (; i < e; i++) {
            int src = g_csr[i];
            float2 v = h2s[(size_t)src * (F2 / 2) + lane];
            acc.x += v.x; acc.y += v.y;
        }
        float dn = g_dinv[n];
        out[(size_t)n * F2 + 2 * lane + 0] = fmaf(dn, acc.x, bx);
        out[(size_t)n * F2 + 2 * lane + 1] = fmaf(dn, acc.y, by);
    }
}

// ---------------- launcher ---------------------------------------------------

extern "C" void kernel_launch(void* const* d_in, const int* in_sizes, int n_in,
                              void* d_out, int out_size) {
    const float* x  = (const float*)d_in[0];
    const void*  ei = d_in[1];                 // int32 or int64 — probed on device
    // d_in[2] = edge_weight (unused: reference overwrites with ones)
    const float* W1 = (const float*)d_in[3];
    const float* b1 = (const float*)d_in[4];
    const float* W2 = (const float*)d_in[5];
    const float* b2 = (const float*)d_in[6];
    float*       out = (float*)d_out;

    int N = in_sizes[0] / F1;
    int E = in_sizes[1] / 2;
    if (N > NMAX) N = NMAX;
    if (E > EMAX) E = EMAX;
    int nb = (N + SCAN_B - 1) / SCAN_B;

    k_detect<<<1, 32>>>((const int*)ei);
    k_zero_cnt<<<(N + 255) / 256, 256>>>(N);
    k_count<<<(E + 255) / 256, 256>>>(ei, E, N);
    k_scan_partial<<<nb, SCAN_B>>>(N);
    k_scan_blk<<<1, 256>>>(nb, N);
    k_scan_apply<<<nb, SCAN_B>>>(N);
    k_fill<<<(E + 255) / 256, 256>>>(E);

    dim3 g1(592, 2);
    k_gemm1<<<g1, 256>>>(x, W1, N);
    k_agg1<<<(N + 7) / 8, 256>>>(b1, N);
    k_gemm2<<<592, 256>>>(W2, N);
    k_agg2<<<(N + 7) / 8, 256>>>(b2, out, N);
}

// round 7
// speedup vs baseline: 2.6671x; 1.7582x over previous
#include <cuda_runtime.h>
#include <cuda_bf16.h>
#include <math.h>

// Problem constants (shapes fixed by the dataset)
#define NMAX  100000
#define EMAX  1600000
#define F1    128
#define F2    64
#define SCAN_B 512
#define NBMAX ((NMAX + SCAN_B - 1) / SCAN_B)   // 196

// ---------------- scratch (static device globals; no allocation allowed) ----
__device__ int    g_is64;                 // 1 if edge_index is int64, else int32
__device__ int    g_cnt[NMAX];
__device__ int    g_bsum[NBMAX];
__device__ int    g_boff[NBMAX];
__device__ int    g_rowstart[NMAX + 1];
__device__ int    g_cursor[NMAX];
__device__ float  g_dinv[NMAX];
__device__ int    g_rows[EMAX];
__device__ int    g_cols[EMAX];
__device__ int    g_csr[EMAX];
__device__ float4 g_h1s[(size_t)NMAX * F1 / 4];     // (x @ W1) * dinv[row]
__device__ float4 g_hidden[(size_t)NMAX * F1 / 4];  // relu(dinv*(sum)+b1)
__device__ float4 g_h2s[(size_t)NMAX * F2 / 4];     // (hidden @ W2) * dinv[row]

// ---------------- build kernels ---------------------------------------------

// Probe dtype of edge_index: int64 values < 2^31 have zero high words.
__global__ void k_detect(const int* __restrict__ ei_raw) {
    if (threadIdx.x == 0 && blockIdx.x == 0) {
        int any = 0;
        for (int i = 0; i < 64; i++) any |= ei_raw[2 * i + 1];
        g_is64 = (any == 0) ? 1 : 0;
    }
}

__global__ void k_zero_cnt(int N) {
    int i = blockIdx.x * blockDim.x + threadIdx.x;
    if (i < N) g_cnt[i] = 0;
}

// Decode edge indices (int32 or int64 per flag), validate, count in-degree.
__global__ void k_count(const void* __restrict__ ei_raw, int E, int N) {
    int e = blockIdx.x * blockDim.x + threadIdx.x;
    if (e >= E) return;
    int r, c;
    if (g_is64) {
        const long long* ei = (const long long*)ei_raw;
        r = (int)ei[e];
        c = (int)ei[(size_t)E + e];
    } else {
        const int* ei = (const int*)ei_raw;
        r = ei[e];
        c = ei[(size_t)E + e];
    }
    if ((unsigned)r >= (unsigned)N || (unsigned)c >= (unsigned)N) {
        g_rows[e] = -1; g_cols[e] = -1;
        return;
    }
    g_rows[e] = r;
    g_cols[e] = c;
    atomicAdd(&g_cnt[c], 1);
}

// Phase 1: per-block sums of counts.
__global__ void __launch_bounds__(SCAN_B) k_scan_partial(int N) {
    __shared__ int red[SCAN_B / 32];
    int b = blockIdx.x, tid = threadIdx.x;
    int i = b * SCAN_B + tid;
    int v = (i < N) ? g_cnt[i] : 0;
    for (int o = 16; o > 0; o >>= 1) v += __shfl_down_sync(0xffffffffu, v, o);
    if ((tid & 31) == 0) red[tid >> 5] = v;
    __syncthreads();
    if (tid < SCAN_B / 32) {
        int s = red[tid];
        for (int o = (SCAN_B / 64); o > 0; o >>= 1) s += __shfl_down_sync(0xffffu, s, o);
        if (tid == 0) g_bsum[b] = s;
    }
}

// Phase 2: single block scans block sums -> exclusive offsets; writes total.
__global__ void __launch_bounds__(256) k_scan_blk(int nb, int N) {
    __shared__ int sh[256];
    int tid = threadIdx.x;
    int v = (tid < nb) ? g_bsum[tid] : 0;
    sh[tid] = v;
    __syncthreads();
    for (int o = 1; o < 256; o <<= 1) {
        int t = (tid >= o) ? sh[tid - o] : 0;
        __syncthreads();
        sh[tid] += t;
        __syncthreads();
    }
    if (tid < nb) g_boff[tid] = sh[tid] - v;       // exclusive
    if (tid == 255) g_rowstart[N] = sh[255];       // total
}

// Phase 3: block-local exclusive scan + offset -> rowstart/cursor/dinv.
__global__ void __launch_bounds__(SCAN_B) k_scan_apply(int N) {
    __shared__ int sh[SCAN_B];
    int b = blockIdx.x, tid = threadIdx.x;
    int i = b * SCAN_B + tid;
    int v = (i < N) ? g_cnt[i] : 0;
    sh[tid] = v;
    __syncthreads();
    for (int o = 1; o < SCAN_B; o <<= 1) {
        int t = (tid >= o) ? sh[tid - o] : 0;
        __syncthreads();
        sh[tid] += t;
        __syncthreads();
    }
    if (i < N) {
        int base = g_boff[b] + sh[tid] - v;        // exclusive prefix
        g_rowstart[i] = base;
        g_cursor[i]   = base;
        g_dinv[i] = rsqrtf((float)(v + 1));        // +1 self loop
    }
}

// Fill CSR: for each valid edge, place its source row into target's bucket.
__global__ void k_fill(int E) {
    int e = blockIdx.x * blockDim.x + threadIdx.x;
    if (e < E) {
        int c = g_cols[e];
        if (c < 0) return;
        int pos = atomicAdd(&g_cursor[c], 1);
        g_csr[pos] = g_rows[e];
    }
}

// ---------------- compute kernels -------------------------------------------

// Register-tiled GEMM1: h1s[n, fh+4*f4..+3] = (x[n] @ W1[:, ...]) * dinv[n].
// Block tile: 32 nodes x 64 features (half of F1, chosen by blockIdx.y).
// 256 threads, each computes 2 nodes x float4 features (8 outputs).
// smem: W half 32KB + x tile 16KB = 48KB. Persistent: W loaded once per block.
__global__ void __launch_bounds__(256) k_gemm1(const float* __restrict__ x,
                                               const float* __restrict__ W1, int N) {
    __shared__ float4 W4s[F1][16];   // 32KB: W1[k][fh + 4*f4 .. +3]
    __shared__ float  xs[32][F1];    // 16KB
    int tid = threadIdx.x;
    int fh = blockIdx.y * 64;
    for (int idx = tid; idx < F1 * 16; idx += 256) {
        int k = idx >> 4, f4 = idx & 15;
        W4s[k][f4] = *(const float4*)(W1 + k * F1 + fh + 4 * f4);
    }
    int nd = tid >> 4;      // 0..15
    int f4 = tid & 15;      // 0..15 -> features fh+4*f4..+3
    int fo = (fh >> 2) + f4;
    int ntiles = (N + 31) >> 5;
    for (int t = blockIdx.x; t < ntiles; t += gridDim.x) {
        int base = t << 5;
        __syncthreads();   // xs reuse (also covers initial W load)
        for (int idx = tid; idx < 32 * (F1 / 4); idx += 256) {
            int r = idx >> 5, c4 = idx & 31;
            int nn = base + r;
            float4 v = (nn < N) ? *(const float4*)(x + (size_t)nn * F1 + 4 * c4)
                                : make_float4(0.f, 0.f, 0.f, 0.f);
            *(float4*)&xs[r][4 * c4] = v;
        }
        __syncthreads();
        float4 a0 = make_float4(0.f, 0.f, 0.f, 0.f);
        float4 a1 = make_float4(0.f, 0.f, 0.f, 0.f);
        #pragma unroll 4
        for (int k = 0; k < F1; k++) {
            float4 w = W4s[k][f4];
            float xa = xs[nd][k];
            float xb = xs[nd + 16][k];
            a0.x = fmaf(xa, w.x, a0.x); a0.y = fmaf(xa, w.y, a0.y);
            a0.z = fmaf(xa, w.z, a0.z); a0.w = fmaf(xa, w.w, a0.w);
            a1.x = fmaf(xb, w.x, a1.x); a1.y = fmaf(xb, w.y, a1.y);
            a1.z = fmaf(xb, w.z, a1.z); a1.w = fmaf(xb, w.w, a1.w);
        }
        int na = base + nd, nb = base + nd + 16;
        if (na < N) {
            float d = g_dinv[na];
            g_h1s[(size_t)na * (F1 / 4) + fo] =
                make_float4(a0.x * d, a0.y * d, a0.z * d, a0.w * d);
        }
        if (nb < N) {
            float d = g_dinv[nb];
            g_h1s[(size_t)nb * (F1 / 4) + fo] =
                make_float4(a1.x * d, a1.y * d, a1.z * d, a1.w * d);
        }
    }
}

// Aggregate layer 1: warp per node, 4-way unrolled gather, fused relu+bias.
__global__ void __launch_bounds__(256) k_agg1(const float* __restrict__ b1, int N) {
    int lane  = threadIdx.x & 31;
    int warp  = (blockIdx.x * blockDim.x + threadIdx.x) >> 5;
    int nwarp = (gridDim.x * blockDim.x) >> 5;
    float bx = b1[4 * lane + 0], by = b1[4 * lane + 1];
    float bz = b1[4 * lane + 2], bw = b1[4 * lane + 3];
    for (int n = warp; n < N; n += nwarp) {
        float4 acc = g_h1s[(size_t)n * (F1 / 4) + lane];   // self loop
        int s = g_rowstart[n], e = g_rowstart[n + 1];
        int i = s;
        for (; i + 4 <= e; i += 4) {
            int s0 = g_csr[i], s1 = g_csr[i + 1], s2 = g_csr[i + 2], s3 = g_csr[i + 3];
            float4 v0 = g_h1s[(size_t)s0 * (F1 / 4) + lane];
            float4 v1 = g_h1s[(size_t)s1 * (F1 / 4) + lane];
            float4 v2 = g_h1s[(size_t)s2 * (F1 / 4) + lane];
            float4 v3 = g_h1s[(size_t)s3 * (F1 / 4) + lane];
            acc.x += v0.x + v1.x + v2.x + v3.x;
            acc.y += v0.y + v1.y + v2.y + v3.y;
            acc.z += v0.z + v1.z + v2.z + v3.z;
            acc.w += v0.w + v1.w + v2.w + v3.w;
        }
        for (; i < e; i++) {
            int src = g_csr[i];
            float4 v = g_h1s[(size_t)src * (F1 / 4) + lane];
            acc.x += v.x; acc.y += v.y; acc.z += v.z; acc.w += v.w;
        }
        float dn = g_dinv[n];
        float4 o;
        o.x = fmaxf(fmaf(dn, acc.x, bx), 0.f);
        o.y = fmaxf(fmaf(dn, acc.y, by), 0.f);
        o.z = fmaxf(fmaf(dn, acc.z, bz), 0.f);
        o.w = fmaxf(fmaf(dn, acc.w, bw), 0.f);
        g_hidden[(size_t)n * (F1 / 4) + lane] = o;
    }
}

// Register-tiled GEMM2: h2s[n] = (hidden[n] @ W2) * dinv[n].
// Block tile: 32 nodes x 64 features (all of F2). Same scheme as gemm1.
__global__ void __launch_bounds__(256) k_gemm2(const float* __restrict__ W2, int N) {
    __shared__ float4 W4s[F1][16];   // 32KB: W2[k][4*f4 .. +3]
    __shared__ float  xs[32][F1];    // 16KB
    int tid = threadIdx.x;
    for (int idx = tid; idx < F1 * 16; idx += 256) {
        int k = idx >> 4, f4 = idx & 15;
        W4s[k][f4] = *(const float4*)(W2 + k * F2 + 4 * f4);
    }
    int nd = tid >> 4;
    int f4 = tid & 15;
    const float* hidden = (const float*)g_hidden;
    int ntiles = (N + 31) >> 5;
    for (int t = blockIdx.x; t < ntiles; t += gridDim.x) {
        int base = t << 5;
        __syncthreads();
        for (int idx = tid; idx < 32 * (F1 / 4); idx += 256) {
            int r = idx >> 5, c4 = idx & 31;
            int nn = base + r;
            float4 v = (nn < N) ? *(const float4*)(hidden + (size_t)nn * F1 + 4 * c4)
                                : make_float4(0.f, 0.f, 0.f, 0.f);
            *(float4*)&xs[r][4 * c4] = v;
        }
        __syncthreads();
        float4 a0 = make_float4(0.f, 0.f, 0.f, 0.f);
        float4 a1 = make_float4(0.f, 0.f, 0.f, 0.f);
        #pragma unroll 4
        for (int k = 0; k < F1; k++) {
            float4 w = W4s[k][f4];
            float xa = xs[nd][k];
            float xb = xs[nd + 16][k];
            a0.x = fmaf(xa, w.x, a0.x); a0.y = fmaf(xa, w.y, a0.y);
            a0.z = fmaf(xa, w.z, a0.z); a0.w = fmaf(xa, w.w, a0.w);
            a1.x = fmaf(xb, w.x, a1.x); a1.y = fmaf(xb, w.y, a1.y);
            a1.z = fmaf(xb, w.z, a1.z); a1.w = fmaf(xb, w.w, a1.w);
        }
        int na = base + nd, nb = base + nd + 16;
        if (na < N) {
            float d = g_dinv[na];
            g_h2s[(size_t)na * (F2 / 4) + f4] =
                make_float4(a0.x * d, a0.y * d, a0.z * d, a0.w * d);
        }
        if (nb < N) {
            float d = g_dinv[nb];
            g_h2s[(size_t)nb * (F2 / 4) + f4] =
                make_float4(a1.x * d, a1.y * d, a1.z * d, a1.w * d);
        }
    }
}

// Aggregate layer 2: warp per node, 4-way unrolled gather, fused bias.
__global__ void __launch_bounds__(256) k_agg2(const float* __restrict__ b2,
                                              float* __restrict__ out, int N) {
    int lane  = threadIdx.x & 31;
    int warp  = (blockIdx.x * blockDim.x + threadIdx.x) >> 5;
    int nwarp = (gridDim.x * blockDim.x) >> 5;
    float bx = b2[2 * lane + 0], by = b2[2 * lane + 1];
    const float2* h2s = (const float2*)g_h2s;
    for (int n = warp; n < N; n += nwarp) {
        float2 acc = h2s[(size_t)n * (F2 / 2) + lane];   // self loop
        int s = g_rowstart[n], e = g_rowstart[n + 1];
        int i = s;
        for (; i + 4 <= e; i += 4) {
            int s0 = g_csr[i], s1 = g_csr[i + 1], s2 = g_csr[i + 2], s3 = g_csr[i + 3];
            float2 v0 = h2s[(size_t)s0 * (F2 / 2) + lane];
            float2 v1 = h2s[(size_t)s1 * (F2 / 2) + lane];
            float2 v2 = h2s[(size_t)s2 * (F2 / 2) + lane];
            float2 v3 = h2s[(size_t)s3 * (F2 / 2) + lane];
            acc.x += v0.x + v1.x + v2.x + v3.x;
            acc.y += v0.y + v1.y + v2.y + v3.y;
        }
        for (; i < e; i++) {
            int src = g_csr[i];
            float2 v = h2s[(size_t)src * (F2 / 2) + lane];
            acc.x += v.x; acc.y += v.y;
        }
        float dn = g_dinv[n];
        out[(size_t)n * F2 + 2 * lane + 0] = fmaf(dn, acc.x, bx);
        out[(size_t)n * F2 + 2 * lane + 1] = fmaf(dn, acc.y, by);
    }
}

// ---------------- launcher ---------------------------------------------------

extern "C" void kernel_launch(void* const* d_in, const int* in_sizes, int n_in,
                              void* d_out, int out_size) {
    const float* x  = (const float*)d_in[0];
    const void*  ei = d_in[1];                 // int32 or int64 — probed on device
    // d_in[2] = edge_weight (unused: reference overwrites with ones)
    const float* W1 = (const float*)d_in[3];
    const float* b1 = (const float*)d_in[4];
    const float* W2 = (const float*)d_in[5];
    const float* b2 = (const float*)d_in[6];
    float*       out = (float*)d_out;

    int N = in_sizes[0] / F1;
    int E = in_sizes[1] / 2;
    if (N > NMAX) N = NMAX;
    if (E > EMAX) E = EMAX;
    int nb = (N + SCAN_B - 1) / SCAN_B;

    k_detect<<<1, 32>>>((const int*)ei);
    k_zero_cnt<<<(N + 255) / 256, 256>>>(N);
    k_count<<<(E + 255) / 256, 256>>>(ei, E, N);
    k_scan_partial<<<nb, SCAN_B>>>(N);
    k_scan_blk<<<1, 256>>>(nb, N);
    k_scan_apply<<<nb, SCAN_B>>>(N);
    k_fill<<<(E + 255) / 256, 256>>>(E);

    dim3 g1(592, 2);
    k_gemm1<<<g1, 256>>>(x, W1, N);
    k_agg1<<<(N + 7) / 8, 256>>>(b1, N);
    k_gemm2<<<592, 256>>>(W2, N);
    k_agg2<<<(N + 7) / 8, 256>>>(b2, out, N);
}